// round 4
// baseline (speedup 1.0000x reference)
#include <cuda_runtime.h>
#include <cuda_bf16.h>

#define BATCH 2
#define SEQ   2048
#define SA    2051          // augmented sequence length
#define HID   1024
#define NH    16
#define HD    64            // head dim
// per-sequence stride for [b, s, hid] or [b, h, s, d] buffers
#define SEQSTR ((size_t)BATCH * SA * HID)   // 4,200,448 floats

// ---------------- scratch (static device memory; no allocation) ------------
__device__ float g_aug [2 * BATCH * SA * HID];   // [seq][b][s][h]
__device__ float g_q   [2 * BATCH * NH * SA * HD];
__device__ float g_k   [2 * BATCH * NH * SA * HD];
__device__ float g_v   [2 * BATCH * NH * SA * HD];
__device__ float g_att [2 * BATCH * SA * HID];   // [dir][b][s][h] row-major
__device__ float g_proj[2 * BATCH * SA * HID];

// ---------------- build augmented sequences --------------------------------
__global__ void build_aug_kernel(const float* __restrict__ cnn,
                                 const float* __restrict__ llm,
                                 const float* __restrict__ ee,
                                 const float* __restrict__ me,
                                 const float* __restrict__ pe,
                                 float* __restrict__ aug)
{
    int s = blockIdx.x, b = blockIdx.y, seq = blockIdx.z;
    const float* src;
    if (s < SEQ) src = (seq == 0 ? cnn : llm) + ((size_t)b * SEQ + s) * HID;
    else         src = (s == SEQ ? ee : (s == SEQ + 1 ? me : pe));
    float* dst = aug + (((size_t)seq * BATCH + b) * SA + s) * HID;
    int j = threadIdx.x * 4;
    float4 v = *(const float4*)(src + j);
    *(float4*)(dst + j) = v;
}

// ---------------- SGEMM: Y = X @ W + bias ----------------------------------
// X: [M, 1024] row-major, W: [1024, 1024] row-major ([in][out]).
// OUT_HEADMAJOR=1 -> Y[b][h][s][d] with m=b*SA+s, n=h*64+d
// OUT_HEADMAJOR=0 -> Y[m][n] row-major
template<int OUT_HEADMAJOR>
__global__ __launch_bounds__(256, 2) void sgemm128(
    const float* __restrict__ X, const float* __restrict__ W,
    const float* __restrict__ bias, float* __restrict__ Y, int M)
{
    __shared__ __align__(16) float Xs[8][128];
    __shared__ __align__(16) float Ws[8][128];
    const int K = 1024;
    int m0 = blockIdx.x * 128, n0 = blockIdx.y * 128;
    int tid = threadIdx.x;
    int tx = tid & 15, ty = tid >> 4;

    float acc[8][8];
#pragma unroll
    for (int i = 0; i < 8; i++)
#pragma unroll
        for (int j = 0; j < 8; j++) acc[i][j] = 0.f;

    int lxr = tid >> 1, lxc = (tid & 1) * 4;      // X tile: 128 rows x 8 k
    int lwr = tid >> 5, lwc = (tid & 31) * 4;     // W tile: 8 k x 128 n

    for (int k0 = 0; k0 < K; k0 += 8) {
        float4 xv = make_float4(0.f, 0.f, 0.f, 0.f);
        int gm = m0 + lxr;
        if (gm < M) xv = *(const float4*)(X + (size_t)gm * K + k0 + lxc);
        Xs[lxc + 0][lxr] = xv.x; Xs[lxc + 1][lxr] = xv.y;
        Xs[lxc + 2][lxr] = xv.z; Xs[lxc + 3][lxr] = xv.w;
        float4 wv = *(const float4*)(W + (size_t)(k0 + lwr) * HID + n0 + lwc);
        *(float4*)(&Ws[lwr][lwc]) = wv;
        __syncthreads();
#pragma unroll
        for (int kk = 0; kk < 8; kk++) {
            float4 a0 = *(const float4*)(&Xs[kk][ty * 8]);
            float4 a1 = *(const float4*)(&Xs[kk][ty * 8 + 4]);
            float4 b0 = *(const float4*)(&Ws[kk][tx * 8]);
            float4 b1 = *(const float4*)(&Ws[kk][tx * 8 + 4]);
            float a[8] = {a0.x, a0.y, a0.z, a0.w, a1.x, a1.y, a1.z, a1.w};
            float bb[8] = {b0.x, b0.y, b0.z, b0.w, b1.x, b1.y, b1.z, b1.w};
#pragma unroll
            for (int i = 0; i < 8; i++)
#pragma unroll
                for (int j = 0; j < 8; j++) acc[i][j] += a[i] * bb[j];
        }
        __syncthreads();
    }

    int n = n0 + tx * 8;
    float bv[8];
#pragma unroll
    for (int j = 0; j < 8; j++) bv[j] = bias[n + j];

#pragma unroll
    for (int i = 0; i < 8; i++) {
        int gm = m0 + ty * 8 + i;
        if (gm >= M) continue;
        float4 o0 = make_float4(acc[i][0] + bv[0], acc[i][1] + bv[1],
                                acc[i][2] + bv[2], acc[i][3] + bv[3]);
        float4 o1 = make_float4(acc[i][4] + bv[4], acc[i][5] + bv[5],
                                acc[i][6] + bv[6], acc[i][7] + bv[7]);
        if (OUT_HEADMAJOR) {
            int b = gm / SA, s = gm - b * SA;
            int h = n >> 6, d0 = n & 63;
            float* yp = Y + (((size_t)b * NH + h) * SA + s) * HD + d0;
            *(float4*)(yp)     = o0;
            *(float4*)(yp + 4) = o1;
        } else {
            float* yp = Y + (size_t)gm * HID + n;
            *(float4*)(yp)     = o0;
            *(float4*)(yp + 4) = o1;
        }
    }
}

// ---------------- flash-style fp32 cross-attention --------------------------
// Q,K,V: [B, NH, SA, HD]; out: [B, SA, HID] row-major (n = h*64 + d)
// Physics biases are per-query constants -> softmax-invariant -> dropped.
__global__ __launch_bounds__(256) void attn_kernel(
    const float* __restrict__ Q, const float* __restrict__ Kx,
    const float* __restrict__ V, float* __restrict__ attout)
{
    __shared__ __align__(16) float Qs[64][68];
    __shared__ __align__(16) float Ks[32][68];
    __shared__ __align__(16) float Vs[32][68];
    __shared__ __align__(16) float Ps[64][34];

    int qt = blockIdx.x, h = blockIdx.y, b = blockIdx.z;
    int tid = threadIdx.x;
    int tx = tid & 15, ty = tid >> 4;
    const size_t headoff = ((size_t)b * NH + h) * (size_t)SA * HD;
    int q0 = qt * 64;

    // load Q tile (zero-pad invalid rows)
    for (int i = tid; i < 64 * 16; i += 256) {
        int r = i >> 4, c = (i & 15) * 4;
        float4 v = make_float4(0.f, 0.f, 0.f, 0.f);
        int gq = q0 + r;
        if (gq < SA) v = *(const float4*)(Q + headoff + (size_t)gq * HD + c);
        *(float4*)(&Qs[r][c]) = v;
    }

    float acc[4][4];
    float mrow[4], lrow[4];
#pragma unroll
    for (int r = 0; r < 4; r++) {
        mrow[r] = -1e30f; lrow[r] = 0.f;
#pragma unroll
        for (int c = 0; c < 4; c++) acc[r][c] = 0.f;
    }
    const float scale = 0.125f;   // 1/sqrt(64)

    for (int k0 = 0; k0 < SA; k0 += 32) {
        __syncthreads();   // previous iter's Ps/Vs reads done before overwrite
        for (int i = tid; i < 32 * 16; i += 256) {
            int r = i >> 4, c = (i & 15) * 4;
            int gk = k0 + r;
            float4 kv = make_float4(0.f, 0.f, 0.f, 0.f), vv = kv;
            if (gk < SA) {
                kv = *(const float4*)(Kx + headoff + (size_t)gk * HD + c);
                vv = *(const float4*)(V  + headoff + (size_t)gk * HD + c);
            }
            *(float4*)(&Ks[r][c]) = kv;
            *(float4*)(&Vs[r][c]) = vv;
        }
        __syncthreads();

        // S tile: rows ty*4+r, cols tx*2+c
        float s[4][2];
#pragma unroll
        for (int r = 0; r < 4; r++) { s[r][0] = 0.f; s[r][1] = 0.f; }
#pragma unroll
        for (int d4 = 0; d4 < HD; d4 += 4) {
            float4 ka = *(const float4*)(&Ks[tx * 2 + 0][d4]);
            float4 kb = *(const float4*)(&Ks[tx * 2 + 1][d4]);
#pragma unroll
            for (int r = 0; r < 4; r++) {
                float4 qv = *(const float4*)(&Qs[ty * 4 + r][d4]);
                s[r][0] += qv.x * ka.x + qv.y * ka.y + qv.z * ka.z + qv.w * ka.w;
                s[r][1] += qv.x * kb.x + qv.y * kb.y + qv.z * kb.z + qv.w * kb.w;
            }
        }
        int kvalid = SA - k0;
#pragma unroll
        for (int r = 0; r < 4; r++)
#pragma unroll
            for (int c = 0; c < 2; c++) {
                int kk = tx * 2 + c;
                s[r][c] = (kk < kvalid) ? s[r][c] * scale : -1e30f;
            }

        // online softmax update (row reduce over 16 lanes)
#pragma unroll
        for (int r = 0; r < 4; r++) {
            float tm = fmaxf(s[r][0], s[r][1]);
            tm = fmaxf(tm, __shfl_xor_sync(0xffffffffu, tm, 1));
            tm = fmaxf(tm, __shfl_xor_sync(0xffffffffu, tm, 2));
            tm = fmaxf(tm, __shfl_xor_sync(0xffffffffu, tm, 4));
            tm = fmaxf(tm, __shfl_xor_sync(0xffffffffu, tm, 8));
            float nm   = fmaxf(mrow[r], tm);
            float corr = __expf(mrow[r] - nm);
            float p0   = __expf(s[r][0] - nm);
            float p1   = __expf(s[r][1] - nm);
            float ts   = p0 + p1;
            ts += __shfl_xor_sync(0xffffffffu, ts, 1);
            ts += __shfl_xor_sync(0xffffffffu, ts, 2);
            ts += __shfl_xor_sync(0xffffffffu, ts, 4);
            ts += __shfl_xor_sync(0xffffffffu, ts, 8);
            lrow[r] = lrow[r] * corr + ts;
            mrow[r] = nm;
#pragma unroll
            for (int c = 0; c < 4; c++) acc[r][c] *= corr;
            Ps[ty * 4 + r][tx * 2 + 0] = p0;
            Ps[ty * 4 + r][tx * 2 + 1] = p1;
        }
        __syncthreads();

        // O += P @ V : rows ty*4+r, d-cols tx*4..+3
#pragma unroll
        for (int kk = 0; kk < 32; kk++) {
            float4 vv = *(const float4*)(&Vs[kk][tx * 4]);
#pragma unroll
            for (int r = 0; r < 4; r++) {
                float p = Ps[ty * 4 + r][kk];
                acc[r][0] += p * vv.x; acc[r][1] += p * vv.y;
                acc[r][2] += p * vv.z; acc[r][3] += p * vv.w;
            }
        }
    }

    // write attended (row-major [b][s][h*64+d])
#pragma unroll
    for (int r = 0; r < 4; r++) {
        int gq = q0 + ty * 4 + r;
        if (gq < SA) {
            float inv = 1.0f / lrow[r];
            float4 o = make_float4(acc[r][0] * inv, acc[r][1] * inv,
                                   acc[r][2] * inv, acc[r][3] * inv);
            *(float4*)(attout + ((size_t)b * SA + gq) * HID + h * HD + tx * 4) = o;
        }
    }
}

// ---------------- residual + LayerNorm epilogue ----------------------------
__global__ __launch_bounds__(256) void ln_kernel(
    const float* __restrict__ aug, const float* __restrict__ proj,
    const float* __restrict__ gamma, const float* __restrict__ beta,
    float* __restrict__ out)
{
    int s = blockIdx.x, b = blockIdx.y, seq = blockIdx.z;
    int tid = threadIdx.x;
    size_t roff = (((size_t)seq * BATCH + b) * SA + s) * HID;
    int j = tid * 4;

    float4 a = *(const float4*)(aug + roff + j);
    float4 p = *(const float4*)(proj + roff + j);
    float4 x = make_float4(a.x + p.x, a.y + p.y, a.z + p.z, a.w + p.w);

    __shared__ float wsum[8];
    float lsum = x.x + x.y + x.z + x.w;
#pragma unroll
    for (int m = 16; m >= 1; m >>= 1) lsum += __shfl_xor_sync(0xffffffffu, lsum, m);
    if ((tid & 31) == 0) wsum[tid >> 5] = lsum;
    __syncthreads();
    float tot = 0.f;
#pragma unroll
    for (int w = 0; w < 8; w++) tot += wsum[w];
    float mean = tot * (1.0f / HID);

    float dx = x.x - mean, dy = x.y - mean, dz = x.z - mean, dw = x.w - mean;
    float lvar = dx * dx + dy * dy + dz * dz + dw * dw;
#pragma unroll
    for (int m = 16; m >= 1; m >>= 1) lvar += __shfl_xor_sync(0xffffffffu, lvar, m);
    __syncthreads();                 // all wsum reads done before re-store
    if ((tid & 31) == 0) wsum[tid >> 5] = lvar;
    __syncthreads();
    float tot2 = 0.f;
#pragma unroll
    for (int w = 0; w < 8; w++) tot2 += wsum[w];
    float rstd = rsqrtf(tot2 * (1.0f / HID) + 1e-5f);

    float4 g = *(const float4*)(gamma + j);
    float4 be = *(const float4*)(beta + j);
    float4 o = make_float4(dx * rstd * g.x + be.x, dy * rstd * g.y + be.y,
                           dz * rstd * g.z + be.z, dw * rstd * g.w + be.w);
    size_t oidx = (size_t)seq * (2ull * SEQ * HID) + ((size_t)b * SEQ + s) * HID + j;
    *(float4*)(out + oidx) = o;
}

// ---------------- launch ----------------------------------------------------
extern "C" void kernel_launch(void* const* d_in, const int* in_sizes, int n_in,
                              void* d_out, int out_size)
{
    const float* cnn = (const float*)d_in[0];
    const float* llm = (const float*)d_in[1];
    const float* Wq  = (const float*)d_in[2];  const float* bq = (const float*)d_in[3];
    const float* Wk  = (const float*)d_in[4];  const float* bk = (const float*)d_in[5];
    const float* Wv  = (const float*)d_in[6];  const float* bv = (const float*)d_in[7];
    const float* Wo  = (const float*)d_in[8];  const float* bo = (const float*)d_in[9];
    const float* ee  = (const float*)d_in[10];
    const float* me  = (const float*)d_in[11];
    const float* pe  = (const float*)d_in[12];
    const float* gamma = (const float*)d_in[13];
    const float* beta  = (const float*)d_in[14];

    float *aug, *q, *k, *v, *att, *proj;
    cudaGetSymbolAddress((void**)&aug,  g_aug);
    cudaGetSymbolAddress((void**)&q,    g_q);
    cudaGetSymbolAddress((void**)&k,    g_k);
    cudaGetSymbolAddress((void**)&v,    g_v);
    cudaGetSymbolAddress((void**)&att,  g_att);
    cudaGetSymbolAddress((void**)&proj, g_proj);

    build_aug_kernel<<<dim3(SA, BATCH, 2), 256>>>(cnn, llm, ee, me, pe, aug);

    const int M = BATCH * SA;                     // 4102
    dim3 gg((M + 127) / 128, HID / 128);          // (33, 8)
    for (int seq = 0; seq < 2; seq++) {
        const float* x = aug + (size_t)seq * SEQSTR;
        sgemm128<1><<<gg, 256>>>(x, Wq, bq, q + (size_t)seq * SEQSTR, M);
        sgemm128<1><<<gg, 256>>>(x, Wk, bk, k + (size_t)seq * SEQSTR, M);
        sgemm128<1><<<gg, 256>>>(x, Wv, bv, v + (size_t)seq * SEQSTR, M);
    }

    dim3 ga((SA + 63) / 64, NH, BATCH);           // (33, 16, 2)
    // dir 0: Q from aug_cnn (seq0), K/V from aug_llm (seq1)
    attn_kernel<<<ga, 256>>>(q, k + SEQSTR, v + SEQSTR, att);
    // dir 1: Q from aug_llm, K/V from aug_cnn
    attn_kernel<<<ga, 256>>>(q + SEQSTR, k, v, att + SEQSTR);

    sgemm128<0><<<gg, 256>>>(att,          Wo, bo, proj,          M);
    sgemm128<0><<<gg, 256>>>(att + SEQSTR, Wo, bo, proj + SEQSTR, M);

    ln_kernel<<<dim3(SEQ, BATCH, 2), 256>>>(aug, proj, gamma, beta, (float*)d_out);
}

// round 6
// speedup vs baseline: 3.0907x; 3.0907x over previous
#include <cuda_runtime.h>
#include <cuda_bf16.h>
#include <cstdint>

#define BATCH 2
#define SEQ   2048
#define SA    2051
#define HID   1024
#define NH    16
#define HD    64
#define SEQSTR ((size_t)BATCH * SA * HID)

// ---------------- scratch ----------------------------------------------------
__device__ float g_aug [2 * BATCH * SA * HID];
__device__ float g_q   [2 * BATCH * NH * SA * HD];
__device__ float g_k   [2 * BATCH * NH * SA * HD];
__device__ float g_v   [2 * BATCH * NH * SA * HD];
__device__ float g_att [2 * BATCH * SA * HID];
__device__ float g_proj[2 * BATCH * SA * HID];

// ---------------- helpers ----------------------------------------------------
__device__ __forceinline__ uint32_t f2tf(float x) {
    uint32_t r;
    asm("cvt.rna.tf32.f32 %0, %1;" : "=r"(r) : "f"(x));
    return r;
}

__device__ __forceinline__ void mma_tf32(float* c, const uint32_t* a, const uint32_t* b) {
    asm volatile(
        "mma.sync.aligned.m16n8k8.row.col.f32.tf32.tf32.f32 "
        "{%0,%1,%2,%3}, {%4,%5,%6,%7}, {%8,%9}, {%0,%1,%2,%3};"
        : "+f"(c[0]), "+f"(c[1]), "+f"(c[2]), "+f"(c[3])
        : "r"(a[0]), "r"(a[1]), "r"(a[2]), "r"(a[3]), "r"(b[0]), "r"(b[1]));
}

// ---------------- build augmented sequences ----------------------------------
__global__ void build_aug_kernel(const float* __restrict__ cnn,
                                 const float* __restrict__ llm,
                                 const float* __restrict__ ee,
                                 const float* __restrict__ me,
                                 const float* __restrict__ pe,
                                 float* __restrict__ aug)
{
    int s = blockIdx.x, b = blockIdx.y, seq = blockIdx.z;
    const float* src;
    if (s < SEQ) src = (seq == 0 ? cnn : llm) + ((size_t)b * SEQ + s) * HID;
    else         src = (s == SEQ ? ee : (s == SEQ + 1 ? me : pe));
    float* dst = aug + (((size_t)seq * BATCH + b) * SA + s) * HID;
    int j = threadIdx.x * 4;
    float4 v = *(const float4*)(src + j);
    *(float4*)(dst + j) = v;
}

// ---------------- TF32 tensor-core SGEMM: Y = X @ W + bias -------------------
// X [M,1024] row-major, W [1024,1024] row-major. BM=BN=128, BK=16, 256 thr.
// 8 warps: 4(m) x 2(n), warp tile 32x64.
template<int OUT_HEADMAJOR>
__global__ __launch_bounds__(256) void sgemm_tf32(
    const float* __restrict__ X, const float* __restrict__ W,
    const float* __restrict__ bias, float* __restrict__ Y, int M)
{
    __shared__ uint32_t As[2][16][136];   // [k][m], pad 136 (=8 mod 32)
    __shared__ uint32_t Bs[2][16][136];   // [k][n]

    const int K = 1024;
    int m0 = blockIdx.x * 128, n0 = blockIdx.y * 128;
    int tid = threadIdx.x;
    int lane = tid & 31, warp = tid >> 5;
    int wm = warp & 3, wn = warp >> 2;
    int g = lane >> 2, t = lane & 3;

    float acc[2][8][4];
#pragma unroll
    for (int mt = 0; mt < 2; mt++)
#pragma unroll
        for (int j = 0; j < 8; j++)
#pragma unroll
            for (int c = 0; c < 4; c++) acc[mt][j][c] = 0.f;

    // loader indices
    int ar = tid >> 2;            // 0..63 (and +64)
    int ac = (tid & 3) * 4;       // k offset within 16
    int br = tid >> 4;            // 0..15 (k)
    int bc = (tid & 15) * 8;      // n offset

    float4 av0, av1, bv0, bv1;
    const float4 z4 = make_float4(0.f, 0.f, 0.f, 0.f);

    // prologue load k0 = 0
    {
        int m1 = m0 + ar, m2 = m0 + ar + 64;
        av0 = (m1 < M) ? *(const float4*)(X + (size_t)m1 * K + ac) : z4;
        av1 = (m2 < M) ? *(const float4*)(X + (size_t)m2 * K + ac) : z4;
        bv0 = *(const float4*)(W + (size_t)br * HID + n0 + bc);
        bv1 = *(const float4*)(W + (size_t)br * HID + n0 + bc + 4);
        As[0][ac + 0][ar] = f2tf(av0.x); As[0][ac + 1][ar] = f2tf(av0.y);
        As[0][ac + 2][ar] = f2tf(av0.z); As[0][ac + 3][ar] = f2tf(av0.w);
        As[0][ac + 0][ar + 64] = f2tf(av1.x); As[0][ac + 1][ar + 64] = f2tf(av1.y);
        As[0][ac + 2][ar + 64] = f2tf(av1.z); As[0][ac + 3][ar + 64] = f2tf(av1.w);
        Bs[0][br][bc + 0] = f2tf(bv0.x); Bs[0][br][bc + 1] = f2tf(bv0.y);
        Bs[0][br][bc + 2] = f2tf(bv0.z); Bs[0][br][bc + 3] = f2tf(bv0.w);
        Bs[0][br][bc + 4] = f2tf(bv1.x); Bs[0][br][bc + 5] = f2tf(bv1.y);
        Bs[0][br][bc + 6] = f2tf(bv1.z); Bs[0][br][bc + 7] = f2tf(bv1.w);
    }
    __syncthreads();

    int cur = 0;
    for (int k0 = 0; k0 < K; k0 += 16) {
        int nk = k0 + 16;
        if (nk < K) {
            int m1 = m0 + ar, m2 = m0 + ar + 64;
            av0 = (m1 < M) ? *(const float4*)(X + (size_t)m1 * K + nk + ac) : z4;
            av1 = (m2 < M) ? *(const float4*)(X + (size_t)m2 * K + nk + ac) : z4;
            bv0 = *(const float4*)(W + (size_t)(nk + br) * HID + n0 + bc);
            bv1 = *(const float4*)(W + (size_t)(nk + br) * HID + n0 + bc + 4);
        }
        // compute on buffer cur
#pragma unroll
        for (int ks = 0; ks < 2; ks++) {
            int kb = ks * 8;
            uint32_t af[2][4], bf[8][2];
#pragma unroll
            for (int mt = 0; mt < 2; mt++) {
                int m = wm * 32 + mt * 16 + g;
                af[mt][0] = As[cur][kb + t][m];
                af[mt][1] = As[cur][kb + t][m + 8];
                af[mt][2] = As[cur][kb + t + 4][m];
                af[mt][3] = As[cur][kb + t + 4][m + 8];
            }
#pragma unroll
            for (int j = 0; j < 8; j++) {
                int n = wn * 64 + j * 8 + g;
                bf[j][0] = Bs[cur][kb + t][n];
                bf[j][1] = Bs[cur][kb + t + 4][n];
            }
#pragma unroll
            for (int mt = 0; mt < 2; mt++)
#pragma unroll
                for (int j = 0; j < 8; j++)
                    mma_tf32(acc[mt][j], af[mt], bf[j]);
        }
        if (nk < K) {
            int nb = cur ^ 1;
            As[nb][ac + 0][ar] = f2tf(av0.x); As[nb][ac + 1][ar] = f2tf(av0.y);
            As[nb][ac + 2][ar] = f2tf(av0.z); As[nb][ac + 3][ar] = f2tf(av0.w);
            As[nb][ac + 0][ar + 64] = f2tf(av1.x); As[nb][ac + 1][ar + 64] = f2tf(av1.y);
            As[nb][ac + 2][ar + 64] = f2tf(av1.z); As[nb][ac + 3][ar + 64] = f2tf(av1.w);
            Bs[nb][br][bc + 0] = f2tf(bv0.x); Bs[nb][br][bc + 1] = f2tf(bv0.y);
            Bs[nb][br][bc + 2] = f2tf(bv0.z); Bs[nb][br][bc + 3] = f2tf(bv0.w);
            Bs[nb][br][bc + 4] = f2tf(bv1.x); Bs[nb][br][bc + 5] = f2tf(bv1.y);
            Bs[nb][br][bc + 6] = f2tf(bv1.z); Bs[nb][br][bc + 7] = f2tf(bv1.w);
            __syncthreads();
            cur = nb;
        }
    }

    // epilogue
#pragma unroll
    for (int mt = 0; mt < 2; mt++) {
#pragma unroll
        for (int rr = 0; rr < 2; rr++) {
            int gm = m0 + wm * 32 + mt * 16 + g + rr * 8;
            if (gm >= M) continue;
#pragma unroll
            for (int j = 0; j < 8; j++) {
                int n = n0 + wn * 64 + j * 8 + t * 2;
                float2 o = make_float2(acc[mt][j][rr * 2] + bias[n],
                                       acc[mt][j][rr * 2 + 1] + bias[n + 1]);
                if (OUT_HEADMAJOR) {
                    int b = gm / SA, s = gm - b * SA;
                    int h = n >> 6, d = n & 63;
                    *(float2*)(Y + (((size_t)b * NH + h) * SA + s) * HD + d) = o;
                } else {
                    *(float2*)(Y + (size_t)gm * HID + n) = o;
                }
            }
        }
    }
}

// ---------------- TF32 flash attention ---------------------------------------
// Q,K,V: [B, NH, SA, HD]; out: [B, SA, HID] (col n = h*64 + d)
// Physics biases are per-row softmax-invariant constants -> dropped.
// Block: 128 threads = 4 warps; BQ=64 (16 rows/warp), BKV=64.
__global__ __launch_bounds__(128) void attn_tf32(
    const float* __restrict__ Q, const float* __restrict__ Kx,
    const float* __restrict__ V, float* __restrict__ attout)
{
    __shared__ uint32_t Ks[64][68];   // pad 68: (4 mod 32)-stride pattern ok
    __shared__ uint32_t Vs[64][72];   // pad 72: (8 mod 32)-stride pattern ok

    int qt = blockIdx.x, h = blockIdx.y, b = blockIdx.z;
    int tid = threadIdx.x;
    int lane = tid & 31, warp = tid >> 5;
    int g = lane >> 2, t = lane & 3;
    const size_t hoff = ((size_t)b * NH + h) * (size_t)SA * HD;
    int q0 = qt * 64;

    // ---- stage Q (scaled by 1/8, tf32) into Ks, grab A-fragments ----
    for (int i = tid; i < 64 * 16; i += 128) {
        int r = i >> 4, c = (i & 15) * 4;
        int gq = q0 + r;
        float4 v = make_float4(0.f, 0.f, 0.f, 0.f);
        if (gq < SA) v = *(const float4*)(Q + hoff + (size_t)gq * HD + c);
        Ks[r][c + 0] = f2tf(v.x * 0.125f); Ks[r][c + 1] = f2tf(v.y * 0.125f);
        Ks[r][c + 2] = f2tf(v.z * 0.125f); Ks[r][c + 3] = f2tf(v.w * 0.125f);
    }
    __syncthreads();
    uint32_t qf[8][4];
    {
        int m = warp * 16;
#pragma unroll
        for (int kc = 0; kc < 8; kc++) {
            qf[kc][0] = Ks[m + g][kc * 8 + t];
            qf[kc][1] = Ks[m + 8 + g][kc * 8 + t];
            qf[kc][2] = Ks[m + g][kc * 8 + t + 4];
            qf[kc][3] = Ks[m + 8 + g][kc * 8 + t + 4];
        }
    }

    float o[8][4];
#pragma unroll
    for (int nd = 0; nd < 8; nd++)
#pragma unroll
        for (int c = 0; c < 4; c++) o[nd][c] = 0.f;
    float mrow0 = -1e30f, mrow1 = -1e30f, lrow0 = 0.f, lrow1 = 0.f;

    for (int k0 = 0; k0 < SA; k0 += 64) {
        __syncthreads();   // previous iteration's smem reads complete
        for (int i = tid; i < 64 * 16; i += 128) {
            int r = i >> 4, c = (i & 15) * 4;
            int gk = k0 + r;
            float4 kv = make_float4(0.f, 0.f, 0.f, 0.f), vv = kv;
            if (gk < SA) {
                kv = *(const float4*)(Kx + hoff + (size_t)gk * HD + c);
                vv = *(const float4*)(V  + hoff + (size_t)gk * HD + c);
            }
            Ks[r][c + 0] = f2tf(kv.x); Ks[r][c + 1] = f2tf(kv.y);
            Ks[r][c + 2] = f2tf(kv.z); Ks[r][c + 3] = f2tf(kv.w);
            Vs[r][c + 0] = f2tf(vv.x); Vs[r][c + 1] = f2tf(vv.y);
            Vs[r][c + 2] = f2tf(vv.z); Vs[r][c + 3] = f2tf(vv.w);
        }
        __syncthreads();

        // ---- S = (Q/8) @ K^T ----
        float s[8][4];
#pragma unroll
        for (int j = 0; j < 8; j++)
#pragma unroll
            for (int c = 0; c < 4; c++) s[j][c] = 0.f;
#pragma unroll
        for (int j = 0; j < 8; j++) {
#pragma unroll
            for (int kc = 0; kc < 8; kc++) {
                uint32_t bf[2];
                bf[0] = Ks[j * 8 + g][kc * 8 + t];
                bf[1] = Ks[j * 8 + g][kc * 8 + t + 4];
                mma_tf32(s[j], qf[kc], bf);
            }
        }

        // ---- mask invalid keys ----
        int kvalid = SA - k0;
        if (kvalid < 64) {
#pragma unroll
            for (int j = 0; j < 8; j++) {
                int c0 = j * 8 + t * 2, c1 = c0 + 1;
                if (c0 >= kvalid) { s[j][0] = -1e30f; s[j][2] = -1e30f; }
                if (c1 >= kvalid) { s[j][1] = -1e30f; s[j][3] = -1e30f; }
            }
        }

        // ---- online softmax (rows g and g+8, spread over 4 lanes) ----
        float tm0 = -1e30f, tm1 = -1e30f;
#pragma unroll
        for (int j = 0; j < 8; j++) {
            tm0 = fmaxf(tm0, fmaxf(s[j][0], s[j][1]));
            tm1 = fmaxf(tm1, fmaxf(s[j][2], s[j][3]));
        }
        tm0 = fmaxf(tm0, __shfl_xor_sync(0xffffffffu, tm0, 1));
        tm0 = fmaxf(tm0, __shfl_xor_sync(0xffffffffu, tm0, 2));
        tm1 = fmaxf(tm1, __shfl_xor_sync(0xffffffffu, tm1, 1));
        tm1 = fmaxf(tm1, __shfl_xor_sync(0xffffffffu, tm1, 2));
        float nm0 = fmaxf(mrow0, tm0), nm1 = fmaxf(mrow1, tm1);
        float corr0 = __expf(mrow0 - nm0), corr1 = __expf(mrow1 - nm1);
        float sum0 = 0.f, sum1 = 0.f;
#pragma unroll
        for (int j = 0; j < 8; j++) {
            s[j][0] = __expf(s[j][0] - nm0);
            s[j][1] = __expf(s[j][1] - nm0);
            s[j][2] = __expf(s[j][2] - nm1);
            s[j][3] = __expf(s[j][3] - nm1);
            sum0 += s[j][0] + s[j][1];
            sum1 += s[j][2] + s[j][3];
        }
        sum0 += __shfl_xor_sync(0xffffffffu, sum0, 1);
        sum0 += __shfl_xor_sync(0xffffffffu, sum0, 2);
        sum1 += __shfl_xor_sync(0xffffffffu, sum1, 1);
        sum1 += __shfl_xor_sync(0xffffffffu, sum1, 2);
        lrow0 = lrow0 * corr0 + sum0;  mrow0 = nm0;
        lrow1 = lrow1 * corr1 + sum1;  mrow1 = nm1;
#pragma unroll
        for (int nd = 0; nd < 8; nd++) {
            o[nd][0] *= corr0; o[nd][1] *= corr0;
            o[nd][2] *= corr1; o[nd][3] *= corr1;
        }

        // ---- O += P @ V (P redistributed to A-fragments via shuffles) ----
        int s0l = (lane & 28) + (t >> 1);   // lane holding cols (2*(t>>1), +1)
#pragma unroll
        for (int j = 0; j < 8; j++) {
            float e0 = __shfl_sync(0xffffffffu, s[j][0], s0l);
            float e1 = __shfl_sync(0xffffffffu, s[j][1], s0l);
            float f0 = __shfl_sync(0xffffffffu, s[j][2], s0l);
            float f1 = __shfl_sync(0xffffffffu, s[j][3], s0l);
            float e2 = __shfl_sync(0xffffffffu, s[j][0], s0l + 2);
            float e3 = __shfl_sync(0xffffffffu, s[j][1], s0l + 2);
            float f2 = __shfl_sync(0xffffffffu, s[j][2], s0l + 2);
            float f3 = __shfl_sync(0xffffffffu, s[j][3], s0l + 2);
            uint32_t af[4];
            af[0] = f2tf((t & 1) ? e1 : e0);   // (g,    t)
            af[1] = f2tf((t & 1) ? f1 : f0);   // (g+8,  t)
            af[2] = f2tf((t & 1) ? e3 : e2);   // (g,    t+4)
            af[3] = f2tf((t & 1) ? f3 : f2);   // (g+8,  t+4)
#pragma unroll
            for (int nd = 0; nd < 8; nd++) {
                uint32_t bf[2];
                bf[0] = Vs[j * 8 + t][nd * 8 + g];
                bf[1] = Vs[j * 8 + t + 4][nd * 8 + g];
                mma_tf32(o[nd], af, bf);
            }
        }
    }

    // ---- write attended rows ----
    float inv0 = 1.0f / lrow0, inv1 = 1.0f / lrow1;
    int row0 = q0 + warp * 16 + g, row1 = row0 + 8;
    int cb = h * HD;
#pragma unroll
    for (int nd = 0; nd < 8; nd++) {
        int col = cb + nd * 8 + t * 2;
        if (row0 < SA) {
            float2 v = make_float2(o[nd][0] * inv0, o[nd][1] * inv0);
            *(float2*)(attout + ((size_t)b * SA + row0) * HID + col) = v;
        }
        if (row1 < SA) {
            float2 v = make_float2(o[nd][2] * inv1, o[nd][3] * inv1);
            *(float2*)(attout + ((size_t)b * SA + row1) * HID + col) = v;
        }
    }
}

// ---------------- residual + LayerNorm epilogue ------------------------------
__global__ __launch_bounds__(256) void ln_kernel(
    const float* __restrict__ aug, const float* __restrict__ proj,
    const float* __restrict__ gamma, const float* __restrict__ beta,
    float* __restrict__ out)
{
    int s = blockIdx.x, b = blockIdx.y, seq = blockIdx.z;
    int tid = threadIdx.x;
    size_t roff = (((size_t)seq * BATCH + b) * SA + s) * HID;
    int j = tid * 4;

    float4 a = *(const float4*)(aug + roff + j);
    float4 p = *(const float4*)(proj + roff + j);
    float4 x = make_float4(a.x + p.x, a.y + p.y, a.z + p.z, a.w + p.w);

    __shared__ float wsum[8];
    float lsum = x.x + x.y + x.z + x.w;
#pragma unroll
    for (int m = 16; m >= 1; m >>= 1) lsum += __shfl_xor_sync(0xffffffffu, lsum, m);
    if ((tid & 31) == 0) wsum[tid >> 5] = lsum;
    __syncthreads();
    float tot = 0.f;
#pragma unroll
    for (int w = 0; w < 8; w++) tot += wsum[w];
    float mean = tot * (1.0f / HID);

    float dx = x.x - mean, dy = x.y - mean, dz = x.z - mean, dw = x.w - mean;
    float lvar = dx * dx + dy * dy + dz * dz + dw * dw;
#pragma unroll
    for (int m = 16; m >= 1; m >>= 1) lvar += __shfl_xor_sync(0xffffffffu, lvar, m);
    __syncthreads();
    if ((tid & 31) == 0) wsum[tid >> 5] = lvar;
    __syncthreads();
    float tot2 = 0.f;
#pragma unroll
    for (int w = 0; w < 8; w++) tot2 += wsum[w];
    float rstd = rsqrtf(tot2 * (1.0f / HID) + 1e-5f);

    float4 g = *(const float4*)(gamma + j);
    float4 be = *(const float4*)(beta + j);
    float4 oo = make_float4(dx * rstd * g.x + be.x, dy * rstd * g.y + be.y,
                            dz * rstd * g.z + be.z, dw * rstd * g.w + be.w);
    size_t oidx = (size_t)seq * (2ull * SEQ * HID) + ((size_t)b * SEQ + s) * HID + j;
    *(float4*)(out + oidx) = oo;
}

// ---------------- launch ------------------------------------------------------
extern "C" void kernel_launch(void* const* d_in, const int* in_sizes, int n_in,
                              void* d_out, int out_size)
{
    const float* cnn = (const float*)d_in[0];
    const float* llm = (const float*)d_in[1];
    const float* Wq  = (const float*)d_in[2];  const float* bq = (const float*)d_in[3];
    const float* Wk  = (const float*)d_in[4];  const float* bk = (const float*)d_in[5];
    const float* Wv  = (const float*)d_in[6];  const float* bv = (const float*)d_in[7];
    const float* Wo  = (const float*)d_in[8];  const float* bo = (const float*)d_in[9];
    const float* ee  = (const float*)d_in[10];
    const float* me  = (const float*)d_in[11];
    const float* pe  = (const float*)d_in[12];
    const float* gamma = (const float*)d_in[13];
    const float* beta  = (const float*)d_in[14];

    float *aug, *q, *k, *v, *att, *proj;
    cudaGetSymbolAddress((void**)&aug,  g_aug);
    cudaGetSymbolAddress((void**)&q,    g_q);
    cudaGetSymbolAddress((void**)&k,    g_k);
    cudaGetSymbolAddress((void**)&v,    g_v);
    cudaGetSymbolAddress((void**)&att,  g_att);
    cudaGetSymbolAddress((void**)&proj, g_proj);

    build_aug_kernel<<<dim3(SA, BATCH, 2), 256>>>(cnn, llm, ee, me, pe, aug);

    const int M = BATCH * SA;                        // 4102
    dim3 gg((M + 127) / 128, HID / 128);             // (33, 8)
    for (int seq = 0; seq < 2; seq++) {
        const float* x = aug + (size_t)seq * SEQSTR;
        sgemm_tf32<1><<<gg, 256>>>(x, Wq, bq, q + (size_t)seq * SEQSTR, M);
        sgemm_tf32<1><<<gg, 256>>>(x, Wk, bk, k + (size_t)seq * SEQSTR, M);
        sgemm_tf32<1><<<gg, 256>>>(x, Wv, bv, v + (size_t)seq * SEQSTR, M);
    }

    dim3 ga((SA + 63) / 64, NH, BATCH);              // (33, 16, 2)
    attn_tf32<<<ga, 128>>>(q, k + SEQSTR, v + SEQSTR, att);          // cnn queries
    attn_tf32<<<ga, 128>>>(q + SEQSTR, k, v, att + SEQSTR);          // llm queries

    sgemm_tf32<0><<<gg, 256>>>(att,          Wo, bo, proj,          M);
    sgemm_tf32<0><<<gg, 256>>>(att + SEQSTR, Wo, bo, proj + SEQSTR, M);

    ln_kernel<<<dim3(SEQ, BATCH, 2), 256>>>(aug, proj, gamma, beta, (float*)d_out);
}